// round 10
// baseline (speedup 1.0000x reference)
#include <cuda_runtime.h>

// Problem shape (fixed by setup_inputs)
#define BQ 4
#define TT 96
#define NN 512
#define ROW_LEN 514              // [beta_logit, gamma_logit, z_0..z_511]
#define EPSV 1e-8f
#define BPB 37                   // 148 = 4 * 37 -> 1 block per SM
#define GRID (BQ * BPB)
#define NSUB 32                  // arrival counters per (b,t): 16 arrivals each
#define SUBPAD 16                // 16 u32 = 64B apart

// Scratch: ping-pong I vector + spread arrival counters.
__device__ float    g_I[2][BQ][NN];
__device__ unsigned g_arrive[BQ][TT][NSUB][SUBPAD];

__global__ void reset_kernel() {
    unsigned* p = &g_arrive[0][0][0][0];
    const int total = BQ * TT * NSUB * SUBPAD;
    const int i = blockIdx.x * blockDim.x + threadIdx.x;
    if (i < total) p[i] = 0u;
}

// --- scoped release/acquire primitives (no fence -> no CCTL.IVALL L1 flush) ---
__device__ __forceinline__ unsigned ld_acq_gpu(const unsigned* p) {
    unsigned v;
    asm volatile("ld.acquire.gpu.global.u32 %0, [%1];" : "=r"(v) : "l"(p) : "memory");
    return v;
}
__device__ __forceinline__ void red_rel_add1(unsigned* p) {
    asm volatile("red.release.gpu.global.add.u32 [%0], 1;" :: "l"(p) : "memory");
}
__device__ __forceinline__ void st_rel_cta_shared(unsigned* p, unsigned v) {
    asm volatile("st.release.cta.shared.u32 [%0], %1;"
                 :: "l"((size_t)__cvta_generic_to_shared(p)), "r"(v) : "memory");
}
__device__ __forceinline__ unsigned ld_acq_cta_shared(const unsigned* p) {
    unsigned v;
    asm volatile("ld.acquire.cta.shared.u32 %0, [%1];"
                 : "=r"(v) : "l"((size_t)__cvta_generic_to_shared(p)) : "memory");
    return v;
}

// ---------------------------------------------------------------------------
// Warp-autonomous fused kernel with delegated polling.
// 148 blocks x 512 threads (1 block/SM):
//   warps 0..13 : one (b,row) each for all 96 steps:
//       prefetch params(t+1) -> softmax(t) in regs -> store epi(t)
//       -> spin on SHARED flag (LDS only, no L2 traffic)
//       -> I(t-1) via __ldcg -> dot(regs) -> SIR update (lane0 regs)
//       -> store g_I/out_view -> red.release arrive (32-way spread counters)
//   warp 14     : sole global poller. ld.acquire the 32 counters of (b,t);
//                 when all reach 16, publish s_flag=t+1 (st.release.cta).
// Causality chain: red.release.gpu -> ld.acquire.gpu -> st.release.cta ->
// ld.acquire.cta (transitive happens-before). Zero fences anywhere.
// ---------------------------------------------------------------------------
__global__ __launch_bounds__(512, 1)
void fused_kernel(const float* __restrict__ x0,
                  const float* __restrict__ params,
                  float* __restrict__ out_view,
                  float* __restrict__ epi) {
    const int blk      = blockIdx.x;
    const int b        = blk / BPB;
    const int jloc     = blk - b * BPB;
    const int rowStart = (jloc * NN) / BPB;
    const int rowEnd   = ((jloc + 1) * NN) / BPB;
    const int lane = threadIdx.x & 31;
    const int wid  = threadIdx.x >> 5;

    __shared__ unsigned s_flag;                    // barriers 0..s_flag-1 done
    if (threadIdx.x == 0) s_flag = 0u;
    __syncthreads();                               // only block-wide sync

    if (wid == 14) {
        // ================= POLLER WARP =================
        for (int t = 0; t < TT - 1; t++) {
            for (;;) {
                const unsigned v = ld_acq_gpu(&g_arrive[b][t][lane][0]);
                if (__all_sync(0xffffffffu, v >= (unsigned)(NN / NSUB))) break;
            }
            if (lane == 0) st_rel_cta_shared(&s_flag, (unsigned)(t + 1));
        }
        return;
    }
    if (wid > 14) return;

    const int row = rowStart + wid;
    if (row >= rowEnd) return;                     // idle warp in 13-row blocks

    // persistent SIR state (lane 0)
    float S = 0.f, I = 0.f, R = 0.f;
    if (lane == 0) {
        const float* xr = x0 + (size_t)(b * NN + row) * 3;
        S = xr[0]; I = xr[1]; R = xr[2];
    }

    const size_t stepStride = (size_t)NN * ROW_LEN;
    const size_t base = ((size_t)(b * TT) * NN + row) * ROW_LEN;

    // prologue: params(0) in regs
    float2 z[8]; float bgz = 0.f;
    {
        const float* p = params + base;
        const float2* p2 = (const float2*)(p + 2);
#pragma unroll
        for (int k = 0; k < 8; k++) z[k] = __ldcs(p2 + lane + 32 * k);
        if (lane < 2) bgz = __ldcs(p + lane);
    }

    for (int t = 0; t < TT; t++) {
        // ---- 1) prefetch params(t+1): in flight through everything below ----
        float2 zn[8]; float bgn = 0.f;
        if (t + 1 < TT) {
            const float* p = params + base + (size_t)(t + 1) * stepStride;
            const float2* p2 = (const float2*)(p + 2);
#pragma unroll
            for (int k = 0; k < 8; k++) zn[k] = __ldcs(p2 + lane + 32 * k);
            if (lane < 2) bgn = __ldcs(p + lane);
        }

        // ---- 2) softmax(t) WITHOUT max-shift (inputs are N(0,1): safe) ----
        float s = 0.f;
#pragma unroll
        for (int k = 0; k < 8; k++) {
            z[k].x = __expf(z[k].x);
            z[k].y = __expf(z[k].y);
            s += z[k].x + z[k].y;
        }
#pragma unroll
        for (int off = 16; off; off >>= 1)
            s += __shfl_xor_sync(0xffffffffu, s, off);
        const float inv = 1.0f / s;

        // store epi(t): streaming stores, never re-read
        float* o = epi + base + (size_t)t * stepStride;
        float sb = 0.f;
        if (lane < 2) {
            sb = 1.0f / (1.0f + __expf(-bgz));
            __stcs(o + lane, sb);
        }
        float2* o2 = (float2*)(o + 2);
#pragma unroll
        for (int k = 0; k < 8; k++) {
            z[k].x *= inv; z[k].y *= inv;          // c(t) stays in registers
            __stcs(o2 + lane + 32 * k, z[k]);
        }
        const float beta  = __shfl_sync(0xffffffffu, sb, 0);
        const float gamma = __shfl_sync(0xffffffffu, sb, 1);

        // ---- 3) wait for barrier(t-1): LDS spin only ----
        if (t > 0) {
            while (ld_acq_cta_shared(&s_flag) < (unsigned)t) { }
        }

        // ---- 4) I(t-1) -> registers (pattern matches c float2 layout) ----
        float2 Iv[8];
        if (t == 0) {
#pragma unroll
            for (int k = 0; k < 8; k++) {
                const int e = 2 * (lane + 32 * k);
                Iv[k].x = x0[(b * NN + e) * 3 + 1];
                Iv[k].y = x0[(b * NN + e + 1) * 3 + 1];
            }
        } else {
            const float2* Ij = (const float2*)&g_I[t & 1][b][0];
#pragma unroll
            for (int k = 0; k < 8; k++) Iv[k] = __ldcg(Ij + lane + 32 * k);
        }

        // ---- 5) dot + SIR update ----
        float acc = 0.f;
#pragma unroll
        for (int k = 0; k < 8; k++)
            acc = fmaf(z[k].x, Iv[k].x, fmaf(z[k].y, Iv[k].y, acc));
#pragma unroll
        for (int off = 16; off; off >>= 1)
            acc += __shfl_xor_sync(0xffffffffu, acc, off);

        if (lane == 0) {
            const float Np = fmaxf(S + I + R, EPSV);
            const float dS = -(beta * S * acc) / Np;
            const float dR = gamma * I;
            const float dI = -dS - dR;
            float St = fmaxf(S + dS, 0.f);
            float It = fmaxf(I + dI, 0.f);
            float Rt = fmaxf(R + dR, 0.f);
            const float sc = Np / fmaxf(St + It + Rt, EPSV);
            S = St * sc; I = It * sc; R = Rt * sc;

            g_I[(t + 1) & 1][b][row] = I;          // ordered by red.release below

            const size_t ov = ((size_t)(b * TT + t) * NN + row) * 3;
            __stcs(out_view + ov,     S);
            __stcs(out_view + ov + 1, I);
            __stcs(out_view + ov + 2, R);
        }

        // ---- 6) arrive on spread counter (16 arrivals per address) ----
        if (t < TT - 1 && lane == 0)
            red_rel_add1(&g_arrive[b][t][row & (NSUB - 1)][0]);

        // rotate prefetch
#pragma unroll
        for (int k = 0; k < 8; k++) z[k] = zn[k];
        bgz = bgn;
    }
}

// ---------------------------------------------------------------------------
// Launch
// ---------------------------------------------------------------------------
extern "C" void kernel_launch(void* const* d_in, const int* in_sizes, int n_in,
                              void* d_out, int out_size) {
    const float* x0;
    const float* params;
    if (in_sizes[0] == BQ * NN * 3) {
        x0     = (const float*)d_in[0];
        params = (const float*)d_in[1];
    } else {
        x0     = (const float*)d_in[1];
        params = (const float*)d_in[0];
    }

    float* out      = (float*)d_out;
    float* out_view = out;                              // (B,T,N,3)
    float* epi      = out + (size_t)BQ * TT * NN * 3;   // (B,T,N,514)

    const int resetN = BQ * TT * NSUB * SUBPAD;
    reset_kernel<<<(resetN + 511) / 512, 512>>>();
    fused_kernel<<<GRID, 512>>>(x0, params, out_view, epi);
}